// round 16
// baseline (speedup 1.0000x reference)
#include <cuda_runtime.h>
#include <cuda_fp16.h>

#define NMAX 100000
#define EMAX 1600000
#define HID 64
#define SCAN_CHUNK 1024   // elements per scan block (256 thr * 4)

// scratch (no cudaMalloc allowed) — double-buffered per layer
__device__ __align__(16) __half g_xp1 [NMAX * HID];
__device__ __align__(16) __half g_xp2 [NMAX * HID];
__device__ float g_als1[NMAX * 2];
__device__ float g_ald1[NMAX * 2];
__device__ float g_als2[NMAX * 2];
__device__ float g_ald2[NMAX * 2];
__device__ int   g_cnt[NMAX];
__device__ int   g_off[NMAX + 1];
__device__ int   g_cur[NMAX];
__device__ int   g_srcs[EMAX];
__device__ int   g_bsums[(NMAX + SCAN_CHUNK - 1) / SCAN_CHUNK];
__device__ int   g_boff [(NMAX + SCAN_CHUNK - 1) / SCAN_CHUNK];
__device__ int   g_is64;

// ---------------------------------------------------------------------------
// Fused: zero the histogram AND detect edge_index dtype (block 0).
// ---------------------------------------------------------------------------
__global__ __launch_bounds__(256)
void detect_zero_kernel(const int* __restrict__ ei, int n)
{
    int i = blockIdx.x * blockDim.x + threadIdx.x;
    if (i < n) g_cnt[i] = 0;
    if (blockIdx.x == 0) {
        __shared__ int s_or;
        if (threadIdx.x == 0) s_or = 0;
        __syncthreads();
        int o = 0;
        for (int k = threadIdx.x; k < 2048; k += 256)
            o |= ei[2 * k + 1];
        if (o) atomicOr(&s_or, 1);
        __syncthreads();
        if (threadIdx.x == 0) g_is64 = (s_or == 0) ? 1 : 0;
    }
}

__device__ __forceinline__ int load_src(const int* ei, int E, int i, int is64)
{
    return is64 ? ei[2 * i] : ei[i];
}
__device__ __forceinline__ int load_dst(const int* ei, int E, int i, int is64)
{
    return is64 ? ei[2 * E + 2 * i] : ei[E + i];
}

__global__ __launch_bounds__(256)
void hist_kernel(const int* __restrict__ ei, int E)
{
    int i = blockIdx.x * blockDim.x + threadIdx.x;
    int is64 = g_is64;
    if (i < E) atomicAdd(&g_cnt[load_dst(ei, E, i, is64)], 1);
}

__device__ __forceinline__ int block_exscan256(int v, int* sh)
{
    const int t = threadIdx.x;
    sh[t] = v;
    __syncthreads();
#pragma unroll
    for (int off = 1; off < 256; off <<= 1) {
        int u = (t >= off) ? sh[t - off] : 0;
        __syncthreads();
        sh[t] += u;
        __syncthreads();
    }
    return sh[t] - v;
}

__global__ __launch_bounds__(256)
void scan_partial(int n)
{
    __shared__ int sh[256];
    const int t = threadIdx.x;
    const int base = blockIdx.x * SCAN_CHUNK + t * 4;
    int s = 0;
#pragma unroll
    for (int j = 0; j < 4; j++)
        if (base + j < n) s += g_cnt[base + j];
    sh[t] = s;
    __syncthreads();
    for (int off = 128; off; off >>= 1) {
        if (t < off) sh[t] += sh[t + off];
        __syncthreads();
    }
    if (t == 0) g_bsums[blockIdx.x] = sh[0];
}

__global__ __launch_bounds__(256)
void scan_bsums(int nb)
{
    __shared__ int sh[256];
    const int t = threadIdx.x;
    int v = (t < nb) ? g_bsums[t] : 0;
    int ex = block_exscan256(v, sh);
    if (t < nb) g_boff[t] = ex;
}

__global__ __launch_bounds__(256)
void scan_final(int n, int E)
{
    __shared__ int sh[256];
    const int t = threadIdx.x;
    const int base = blockIdx.x * SCAN_CHUNK + t * 4;
    int c[4];
    int s = 0;
#pragma unroll
    for (int j = 0; j < 4; j++) {
        c[j] = (base + j < n) ? g_cnt[base + j] : 0;
        s += c[j];
    }
    int ex = block_exscan256(s, sh) + g_boff[blockIdx.x];
#pragma unroll
    for (int j = 0; j < 4; j++) {
        if (base + j < n) {
            g_off[base + j] = ex;
            g_cur[base + j] = ex;
        }
        ex += c[j];
    }
    if (blockIdx.x == 0 && t == 0) g_off[n] = E;
}

__global__ __launch_bounds__(256)
void scatter_kernel(const int* __restrict__ ei, int E)
{
    int i = blockIdx.x * blockDim.x + threadIdx.x;
    if (i >= E) return;
    int is64 = g_is64;
    int d = load_dst(ei, E, i, is64);
    int s = load_src(ei, E, i, is64);
    int pos = atomicAdd(&g_cur[d], 1);
    g_srcs[pos] = s;
}

// ---------------------------------------------------------------------------
// Layer-1 GEMM + attention-logit epilogue (xp1/als1/ald1).
// ---------------------------------------------------------------------------
__global__ __launch_bounds__(256)
void gemm1_kernel(const float* __restrict__ X,
                  const float* __restrict__ W,
                  const float* __restrict__ att_s,
                  const float* __restrict__ att_d,
                  int n)
{
    const int K = 128;
    __shared__ __align__(16) float sW[64 * 64];
    __shared__ __align__(16) float sXT[64][132];

    const int tid = threadIdx.x;
    const int cx  = tid & 15;
    const int ry  = tid >> 4;
    const int row0 = blockIdx.x * 128;

    float C[8][4];
#pragma unroll
    for (int i = 0; i < 8; i++)
#pragma unroll
        for (int j = 0; j < 4; j++) C[i][j] = 0.f;

    for (int kc = 0; kc < K; kc += 64) {
        __syncthreads();
#pragma unroll
        for (int q = 0; q < 4; q++) {
            int idx4 = tid + q * 256;
            float4 v = *(const float4*)&W[kc * 64 + idx4 * 4];
            *(float4*)&sW[idx4 * 4] = v;
        }
#pragma unroll
        for (int q = 0; q < 8; q++) {
            int lin = tid + q * 256;
            int r  = lin >> 4;
            int c4 = lin & 15;
            int gr = row0 + r; if (gr > n - 1) gr = n - 1;
            float4 v = *(const float4*)&X[(long long)gr * K + kc + c4 * 4];
            sXT[c4 * 4 + 0][r] = v.x;
            sXT[c4 * 4 + 1][r] = v.y;
            sXT[c4 * 4 + 2][r] = v.z;
            sXT[c4 * 4 + 3][r] = v.w;
        }
        __syncthreads();
#pragma unroll
        for (int k = 0; k < 64; k++) {
            float4 wv = *(const float4*)&sW[k * 64 + cx * 4];
            float4 xa = *(const float4*)&sXT[k][ry * 8];
            float4 xb = *(const float4*)&sXT[k][ry * 8 + 4];
            float xr[8] = {xa.x, xa.y, xa.z, xa.w, xb.x, xb.y, xb.z, xb.w};
#pragma unroll
            for (int i = 0; i < 8; i++) {
                C[i][0] = fmaf(xr[i], wv.x, C[i][0]);
                C[i][1] = fmaf(xr[i], wv.y, C[i][1]);
                C[i][2] = fmaf(xr[i], wv.z, C[i][2]);
                C[i][3] = fmaf(xr[i], wv.w, C[i][3]);
            }
        }
    }

    const int h    = cx >> 3;
    const int lane = tid & 31;
    float asv[4], adv[4];
#pragma unroll
    for (int j = 0; j < 4; j++) {
        asv[j] = __ldg(&att_s[cx * 4 + j]);
        adv[j] = __ldg(&att_d[cx * 4 + j]);
    }

#pragma unroll
    for (int i = 0; i < 8; i++) {
        float alsv = 0.f, aldv = 0.f;
#pragma unroll
        for (int j = 0; j < 4; j++) {
            alsv = fmaf(C[i][j], asv[j], alsv);
            aldv = fmaf(C[i][j], adv[j], aldv);
        }
#pragma unroll
        for (int off = 4; off; off >>= 1) {
            alsv += __shfl_down_sync(0xffffffffu, alsv, off, 8);
            aldv += __shfl_down_sync(0xffffffffu, aldv, off, 8);
        }
        int row = row0 + ry * 8 + i;
        if (row < n) {
            if ((lane & 7) == 0) {
                g_als1[row * 2 + h] = alsv;
                g_ald1[row * 2 + h] = aldv;
            }
            __half2 p0 = __floats2half2_rn(C[i][0], C[i][1]);
            __half2 p1 = __floats2half2_rn(C[i][2], C[i][3]);
            __half2* dst = reinterpret_cast<__half2*>(&g_xp1[row * HID + cx * 4]);
            dst[0] = p0;
            dst[1] = p1;
        }
    }
}

// ---------------------------------------------------------------------------
// FUSED gather1 + gemm2 + layer-2 logits.
// Gather (v3 structure, layer-1 buffers) -> h row in registers (2 f32/lane,
// bias1 + ELU applied) -> warp-local h @ W2 via shfl broadcast + smem W2
// -> xp2 (fp16), als2/ald2. g_h is eliminated entirely.
// ---------------------------------------------------------------------------
__global__ __launch_bounds__(256)
void fused_gather1_gemm2(const float* __restrict__ bias1,
                         const float* __restrict__ W2,
                         const float* __restrict__ att_s2,
                         const float* __restrict__ att_d2,
                         int n)
{
    __shared__ __align__(16) float sW2[64 * 64];   // 16 KB
    // cooperative W2 load (L1-cached after first block per SM)
    for (int q = threadIdx.x; q < 1024; q += 256) {
        float4 v = *(const float4*)&W2[q * 4];
        *(float4*)&sW2[q * 4] = v;
    }
    __syncthreads();

    int warp = (blockIdx.x * 256 + threadIdx.x) >> 5;
    int lane = threadIdx.x & 31;
    if (warp >= n) return;
    const int node = warp;
    const int h  = lane >> 4;
    const int hl = lane & 15;

    const __half2* __restrict__ xp2v =
        reinterpret_cast<const __half2*>(g_xp1) + lane;

    const float ald_h = __ldg(&g_ald1[node * 2 + h]);

    // self loop
    float t0 = __ldg(&g_als1[node * 2 + h]) + ald_h;
    t0 = fmaxf(t0, 0.2f * t0);
    float wself = __expf(t0);
    float2 xv = __half22float2(xp2v[node * 32]);
    float a0 = xv.x * wself, a1 = xv.y * wself;
    float segl = 0.f;

    const int beg = g_off[node];
    const int end = g_off[node + 1];
    for (int i = beg; i < end; i += 16) {
        int idx = i + hl;
        bool valid = idx < end;
        int sidx = valid ? __ldg(&g_srcs[idx]) : 0;
        float al = __ldg(&g_als1[sidx * 2 + h]);
        float tt = al + ald_h;
        tt = fmaxf(tt, 0.2f * tt);
        float w = valid ? __expf(tt) : 0.f;
        segl += w;

#pragma unroll
        for (int jb = 0; jb < 16; jb += 8) {
            float  ww[8];
            float2 xs[8];
#pragma unroll
            for (int j = 0; j < 8; j++) {
                ww[j] = __shfl_sync(0xffffffffu, w,    jb + j, 16);
                int s = __shfl_sync(0xffffffffu, sidx, jb + j, 16);
                xs[j] = __half22float2(xp2v[s * 32]);
            }
#pragma unroll
            for (int j = 0; j < 8; j++) {
                a0 = fmaf(xs[j].x, ww[j], a0);
                a1 = fmaf(xs[j].y, ww[j], a1);
            }
        }
    }

#pragma unroll
    for (int off = 8; off; off >>= 1)
        segl += __shfl_xor_sync(0xffffffffu, segl, off, 16);
    float seg = segl + wself;

    // h row (bias1 + ELU), fp32 in registers
    float inv = 1.f / (seg + 1e-16f);
    float2 bv = *(const float2*)&bias1[lane * 2];
    float v0 = a0 * inv + bv.x;
    float v1 = a1 * inv + bv.y;
    v0 = v0 > 0.f ? v0 : expm1f(v0);
    v1 = v1 > 0.f ? v1 : expm1f(v1);

    // warp-local h @ W2 (64x64): lane owns output cols 2*lane, 2*lane+1
    float o0 = 0.f, o1 = 0.f;
#pragma unroll
    for (int ks = 0; ks < 32; ks++) {
        float h0 = __shfl_sync(0xffffffffu, v0, ks, 32);  // h[2ks]
        float h1 = __shfl_sync(0xffffffffu, v1, ks, 32);  // h[2ks+1]
        float2 w0 = *(const float2*)&sW2[(2 * ks)     * 64 + 2 * lane];
        float2 w1 = *(const float2*)&sW2[(2 * ks + 1) * 64 + 2 * lane];
        o0 = fmaf(h0, w0.x, o0); o0 = fmaf(h1, w1.x, o0);
        o1 = fmaf(h0, w0.y, o1); o1 = fmaf(h1, w1.y, o1);
    }

    // layer-2 attention logits: head of col 2*lane = lane/16 = h
    float as0 = __ldg(&att_s2[2 * lane]);
    float as1 = __ldg(&att_s2[2 * lane + 1]);
    float ad0 = __ldg(&att_d2[2 * lane]);
    float ad1 = __ldg(&att_d2[2 * lane + 1]);
    float alsv = o0 * as0 + o1 * as1;
    float aldv = o0 * ad0 + o1 * ad1;
#pragma unroll
    for (int off = 8; off; off >>= 1) {
        alsv += __shfl_down_sync(0xffffffffu, alsv, off, 16);
        aldv += __shfl_down_sync(0xffffffffu, aldv, off, 16);
    }
    if (hl == 0) {
        g_als2[node * 2 + h] = alsv;
        g_ald2[node * 2 + h] = aldv;
    }
    reinterpret_cast<__half2*>(g_xp2)[node * 32 + lane] =
        __floats2half2_rn(o0, o1);
}

// ---------------------------------------------------------------------------
// Gather pass 2 (v3 structure, layer-2 buffers) -> final output.
// ---------------------------------------------------------------------------
__global__ __launch_bounds__(256)
void gather2_kernel(const float* __restrict__ bias,
                    float* __restrict__ out, int n)
{
    int warp = (blockIdx.x * 256 + threadIdx.x) >> 5;
    int lane = threadIdx.x & 31;
    if (warp >= n) return;
    const int node = warp;
    const int h  = lane >> 4;
    const int hl = lane & 15;

    const __half2* __restrict__ xp2v =
        reinterpret_cast<const __half2*>(g_xp2) + lane;

    const float ald_h = __ldg(&g_ald2[node * 2 + h]);

    float t0 = __ldg(&g_als2[node * 2 + h]) + ald_h;
    t0 = fmaxf(t0, 0.2f * t0);
    float wself = __expf(t0);
    float2 xv = __half22float2(xp2v[node * 32]);
    float a0 = xv.x * wself, a1 = xv.y * wself;
    float segl = 0.f;

    const int beg = g_off[node];
    const int end = g_off[node + 1];
    for (int i = beg; i < end; i += 16) {
        int idx = i + hl;
        bool valid = idx < end;
        int sidx = valid ? __ldg(&g_srcs[idx]) : 0;
        float al = __ldg(&g_als2[sidx * 2 + h]);
        float tt = al + ald_h;
        tt = fmaxf(tt, 0.2f * tt);
        float w = valid ? __expf(tt) : 0.f;
        segl += w;

#pragma unroll
        for (int jb = 0; jb < 16; jb += 8) {
            float  ww[8];
            float2 xs[8];
#pragma unroll
            for (int j = 0; j < 8; j++) {
                ww[j] = __shfl_sync(0xffffffffu, w,    jb + j, 16);
                int s = __shfl_sync(0xffffffffu, sidx, jb + j, 16);
                xs[j] = __half22float2(xp2v[s * 32]);
            }
#pragma unroll
            for (int j = 0; j < 8; j++) {
                a0 = fmaf(xs[j].x, ww[j], a0);
                a1 = fmaf(xs[j].y, ww[j], a1);
            }
        }
    }

#pragma unroll
    for (int off = 8; off; off >>= 1)
        segl += __shfl_xor_sync(0xffffffffu, segl, off, 16);
    float seg = segl + wself;

    float inv = 1.f / (seg + 1e-16f);
    float2 bv = *(const float2*)&bias[lane * 2];
    float v0 = a0 * inv + bv.x;
    float v1 = a1 * inv + bv.y;
    *(float2*)&out[node * HID + lane * 2] = make_float2(v0, v1);
}

extern "C" void kernel_launch(void* const* d_in, const int* in_sizes, int n_in,
                              void* d_out, int out_size)
{
    const float* x   = (const float*)d_in[0];
    const int*   ei  = (const int*)d_in[1];
    const float* W1  = (const float*)d_in[2];
    const float* as1 = (const float*)d_in[3];
    const float* ad1 = (const float*)d_in[4];
    const float* b1  = (const float*)d_in[5];
    const float* W2  = (const float*)d_in[6];
    const float* as2 = (const float*)d_in[7];
    const float* ad2 = (const float*)d_in[8];
    const float* b2  = (const float*)d_in[9];

    const int n = in_sizes[0] / 128;          // 100000
    const int E = in_sizes[1] / 2;            // 1600000
    const int gb  = (n + 127) / 128;
    const int nbl = (n + 255) / 256;
    const int ebl = (E + 255) / 256;
    const int wbl = ((n * 32) + 255) / 256;
    const int sb  = (n + SCAN_CHUNK - 1) / SCAN_CHUNK;

    static cudaStream_t sCsr = nullptr, sMain = nullptr;
    static cudaEvent_t evFork = nullptr, evCsr = nullptr, evDone = nullptr;
    if (!sCsr) {
        cudaStreamCreateWithFlags(&sCsr,  cudaStreamNonBlocking);
        cudaStreamCreateWithFlags(&sMain, cudaStreamNonBlocking);
        cudaEventCreateWithFlags(&evFork, cudaEventDisableTiming);
        cudaEventCreateWithFlags(&evCsr,  cudaEventDisableTiming);
        cudaEventCreateWithFlags(&evDone, cudaEventDisableTiming);
    }

    cudaEventRecord(evFork, 0);
    cudaStreamWaitEvent(sCsr,  evFork, 0);
    cudaStreamWaitEvent(sMain, evFork, 0);

    // CSR chain on sCsr; gemm1 concurrently on sMain
    detect_zero_kernel<<<nbl, 256, 0, sCsr>>>(ei, n);
    hist_kernel<<<ebl, 256, 0, sCsr>>>(ei, E);
    gemm1_kernel<<<gb, 256, 0, sMain>>>(x, W1, as1, ad1, n);
    scan_partial<<<sb, 256, 0, sCsr>>>(n);
    scan_bsums<<<1, 256, 0, sCsr>>>(sb);
    scan_final<<<sb, 256, 0, sCsr>>>(n, E);
    scatter_kernel<<<ebl, 256, 0, sCsr>>>(ei, E);
    cudaEventRecord(evCsr, sCsr);

    // fused gather1 + gemm2 (needs gemm1 + CSR), then gather2
    cudaStreamWaitEvent(sMain, evCsr, 0);
    fused_gather1_gemm2<<<wbl, 256, 0, sMain>>>(b1, W2, as2, ad2, n);
    gather2_kernel<<<wbl, 256, 0, sMain>>>(b2, (float*)d_out, n);

    cudaEventRecord(evDone, sMain);
    cudaStreamWaitEvent(0, evDone, 0);
}

// round 17
// speedup vs baseline: 1.2162x; 1.2162x over previous
#include <cuda_runtime.h>
#include <cuda_fp16.h>

#define NMAX 100000
#define EMAX 1600000
#define HID 64
#define SCAN_CHUNK 1024
#define SCAN_NBLK ((NMAX + SCAN_CHUNK - 1) / SCAN_CHUNK)

typedef unsigned long long u64;

// scratch (no cudaMalloc allowed) — double-buffered per layer
__device__ __align__(16) __half g_xp1 [NMAX * HID];
__device__ __align__(16) __half g_xp2 [NMAX * HID];
__device__ __align__(16) float  g_h   [NMAX * HID];
__device__ float g_als1[NMAX * 2];
__device__ float g_ald1[NMAX * 2];
__device__ float g_als2[NMAX * 2];
__device__ float g_ald2[NMAX * 2];
__device__ int   g_cnt[NMAX];
__device__ int   g_off[NMAX + 1];
__device__ int   g_cur[NMAX];
__device__ int   g_srcs[EMAX];
__device__ unsigned g_scan_pub[SCAN_NBLK];
__device__ int   g_is64;

// ---------------------------------------------------------------------------
// packed f32x2 helpers (FFMA2 — PTX-only; exact fp32 math)
// ---------------------------------------------------------------------------
__device__ __forceinline__ void ffma2(u64 &d, u64 a, u64 b)
{
    asm("fma.rn.f32x2 %0, %1, %2, %0;" : "+l"(d) : "l"(a), "l"(b));
}
__device__ __forceinline__ u64 dup2(float x)
{
    u64 d; asm("mov.b64 %0, {%1, %1};" : "=l"(d) : "f"(x)); return d;
}
__device__ __forceinline__ float2 unpack2(u64 d)
{
    float2 f; asm("mov.b64 {%0, %1}, %2;" : "=f"(f.x), "=f"(f.y) : "l"(d));
    return f;
}

// ---------------------------------------------------------------------------
// Fused: zero histogram + scan flags AND detect edge_index dtype (block 0).
// ---------------------------------------------------------------------------
__global__ __launch_bounds__(256)
void detect_zero_kernel(const int* __restrict__ ei, int n)
{
    int i = blockIdx.x * blockDim.x + threadIdx.x;
    if (i < n) g_cnt[i] = 0;
    if (i < SCAN_NBLK) g_scan_pub[i] = 0u;
    if (blockIdx.x == 0) {
        __shared__ int s_or;
        if (threadIdx.x == 0) s_or = 0;
        __syncthreads();
        int o = 0;
        for (int k = threadIdx.x; k < 2048; k += 256)
            o |= ei[2 * k + 1];
        if (o) atomicOr(&s_or, 1);
        __syncthreads();
        if (threadIdx.x == 0) g_is64 = (s_or == 0) ? 1 : 0;
    }
}

__device__ __forceinline__ int load_src(const int* ei, int E, int i, int is64)
{
    return is64 ? ei[2 * i] : ei[i];
}
__device__ __forceinline__ int load_dst(const int* ei, int E, int i, int is64)
{
    return is64 ? ei[2 * E + 2 * i] : ei[E + i];
}

__global__ __launch_bounds__(256)
void hist_kernel(const int* __restrict__ ei, int E)
{
    int i = blockIdx.x * blockDim.x + threadIdx.x;
    int is64 = g_is64;
    if (i < E) atomicAdd(&g_cnt[load_dst(ei, E, i, is64)], 1);
}

__device__ __forceinline__ int block_exscan256(int v, int* sh)
{
    const int t = threadIdx.x;
    sh[t] = v;
    __syncthreads();
#pragma unroll
    for (int off = 1; off < 256; off <<= 1) {
        int u = (t >= off) ? sh[t - off] : 0;
        __syncthreads();
        sh[t] += u;
        __syncthreads();
    }
    return sh[t] - v;
}

// ---------------------------------------------------------------------------
// Single-pass exclusive scan (decoupled lookback). One kernel; 98 blocks,
// all resident -> lookback always makes progress. pub word = flag<<30 | sum.
// ---------------------------------------------------------------------------
__global__ __launch_bounds__(256)
void scan_lookback(int n, int E)
{
    __shared__ int sh[256];
    __shared__ int s_run;
    const int t = threadIdx.x;
    const int b = blockIdx.x;
    const int base = b * SCAN_CHUNK + t * 4;

    int c[4];
    int s = 0;
#pragma unroll
    for (int j = 0; j < 4; j++) {
        c[j] = (base + j < n) ? g_cnt[base + j] : 0;
        s += c[j];
    }
    int ex = block_exscan256(s, sh);
    int total = sh[255];

    // publish aggregate (block 0 publishes its inclusive prefix directly)
    if (t == 0) {
        *(volatile unsigned*)&g_scan_pub[b] =
            (b == 0 ? (2u << 30) : (1u << 30)) | (unsigned)total;
    }

    // warp 0: lookback, 32 predecessors at a time
    if (t < 32) {
        int run = 0;
        int bb = b - 1;
        while (bb >= 0) {
            int p = bb - t;
            unsigned v = 0;
            if (p >= 0) {
                do { v = *(volatile unsigned*)&g_scan_pub[p]; } while (v == 0u);
            }
            unsigned bal = __ballot_sync(0xffffffffu,
                                         p >= 0 && (v >> 30) == 2u);
            int cut = bal ? (__ffs(bal) - 1) : 32;
            int contrib = (p >= 0 && t <= cut) ? (int)(v & 0x3FFFFFFFu) : 0;
#pragma unroll
            for (int off = 16; off; off >>= 1)
                contrib += __shfl_xor_sync(0xffffffffu, contrib, off);
            run += contrib;
            if (cut < 32) break;
            bb -= 32;
        }
        if (t == 0) {
            *(volatile unsigned*)&g_scan_pub[b] =
                (2u << 30) | (unsigned)(run + total);
            s_run = run;
        }
    }
    __syncthreads();

    int off0 = s_run + ex;
#pragma unroll
    for (int j = 0; j < 4; j++) {
        if (base + j < n) {
            g_off[base + j] = off0;
            g_cur[base + j] = off0;
        }
        off0 += c[j];
    }
    if (b == 0 && t == 0) g_off[n] = E;
}

__global__ __launch_bounds__(256)
void scatter_kernel(const int* __restrict__ ei, int E)
{
    int i = blockIdx.x * blockDim.x + threadIdx.x;
    if (i >= E) return;
    int is64 = g_is64;
    int d = load_dst(ei, E, i, is64);
    int s = load_src(ei, E, i, is64);
    int pos = atomicAdd(&g_cur[d], 1);
    g_srcs[pos] = s;
}

// ---------------------------------------------------------------------------
// Fused GEMM + attention-logit epilogue, FFMA2 row-pair packed accumulators.
// LAYER selects buffers (1: X->xp1/als1/ald1; 2: g_h->xp2/als2/ald2).
// Block: 256 thr, tile 128 rows x 64 cols, thread tile 8 rows x 4 cols.
// Inner per k: 3 LDS.128 + 4 dup-MOV + 16 FFMA2 (row pairs come free from
// the float4 row loads).
// ---------------------------------------------------------------------------
template<int K, int LAYER>
__global__ __launch_bounds__(256, 3)
void gemm_al_kernel(const float* __restrict__ Xin,
                    const float* __restrict__ W,
                    const float* __restrict__ att_s,
                    const float* __restrict__ att_d,
                    int n)
{
    const float* __restrict__ X = (LAYER == 1) ? Xin : g_h;
    __half* __restrict__ xp  = (LAYER == 1) ? g_xp1 : g_xp2;
    float*  __restrict__ als = (LAYER == 1) ? g_als1 : g_als2;
    float*  __restrict__ ald = (LAYER == 1) ? g_ald1 : g_ald2;

    __shared__ __align__(16) float sW[64 * 64];
    __shared__ __align__(16) float sXT[64][132];

    const int tid = threadIdx.x;
    const int cx  = tid & 15;
    const int ry  = tid >> 4;
    const int row0 = blockIdx.x * 128;

    u64 P[4][4];   // row-pair packed accumulators: P[p][j] = (C[2p][j], C[2p+1][j])
#pragma unroll
    for (int p = 0; p < 4; p++)
#pragma unroll
        for (int j = 0; j < 4; j++) P[p][j] = 0ull;

    for (int kc = 0; kc < K; kc += 64) {
        __syncthreads();
#pragma unroll
        for (int q = 0; q < 4; q++) {
            int idx4 = tid + q * 256;
            float4 v = *(const float4*)&W[kc * 64 + idx4 * 4];
            *(float4*)&sW[idx4 * 4] = v;
        }
#pragma unroll
        for (int q = 0; q < 8; q++) {
            int lin = tid + q * 256;
            int r  = lin >> 4;
            int c4 = lin & 15;
            int gr = row0 + r; if (gr > n - 1) gr = n - 1;
            float4 v = *(const float4*)&X[(long long)gr * K + kc + c4 * 4];
            sXT[c4 * 4 + 0][r] = v.x;
            sXT[c4 * 4 + 1][r] = v.y;
            sXT[c4 * 4 + 2][r] = v.z;
            sXT[c4 * 4 + 3][r] = v.w;
        }
        __syncthreads();
#pragma unroll
        for (int k = 0; k < 64; k++) {
            float4 wv = *(const float4*)&sW[k * 64 + cx * 4];
            u64 wd0 = dup2(wv.x), wd1 = dup2(wv.y),
                wd2 = dup2(wv.z), wd3 = dup2(wv.w);
            ulonglong2 xpa = *(const ulonglong2*)&sXT[k][ry * 8];
            ulonglong2 xpb = *(const ulonglong2*)&sXT[k][ry * 8 + 4];
            u64 xr[4] = {xpa.x, xpa.y, xpb.x, xpb.y};
#pragma unroll
            for (int p = 0; p < 4; p++) {
                ffma2(P[p][0], xr[p], wd0);
                ffma2(P[p][1], xr[p], wd1);
                ffma2(P[p][2], xr[p], wd2);
                ffma2(P[p][3], xr[p], wd3);
            }
        }
    }

    // unpack
    float C[8][4];
#pragma unroll
    for (int p = 0; p < 4; p++)
#pragma unroll
        for (int j = 0; j < 4; j++) {
            float2 f = unpack2(P[p][j]);
            C[2 * p + 0][j] = f.x;
            C[2 * p + 1][j] = f.y;
        }

    const int h    = cx >> 3;
    const int lane = tid & 31;
    float asv[4], adv[4];
#pragma unroll
    for (int j = 0; j < 4; j++) {
        asv[j] = __ldg(&att_s[cx * 4 + j]);
        adv[j] = __ldg(&att_d[cx * 4 + j]);
    }

#pragma unroll
    for (int i = 0; i < 8; i++) {
        float alsv = 0.f, aldv = 0.f;
#pragma unroll
        for (int j = 0; j < 4; j++) {
            alsv = fmaf(C[i][j], asv[j], alsv);
            aldv = fmaf(C[i][j], adv[j], aldv);
        }
#pragma unroll
        for (int off = 4; off; off >>= 1) {
            alsv += __shfl_down_sync(0xffffffffu, alsv, off, 8);
            aldv += __shfl_down_sync(0xffffffffu, aldv, off, 8);
        }
        int row = row0 + ry * 8 + i;
        if (row < n) {
            if ((lane & 7) == 0) {
                als[row * 2 + h] = alsv;
                ald[row * 2 + h] = aldv;
            }
            __half2 p0 = __floats2half2_rn(C[i][0], C[i][1]);
            __half2 p1 = __floats2half2_rn(C[i][2], C[i][3]);
            __half2* dst = reinterpret_cast<__half2*>(&xp[row * HID + cx * 4]);
            dst[0] = p0;
            dst[1] = p1;
        }
    }
}

// ---------------------------------------------------------------------------
// Gather pass (204.9us winner, v3), buffer-parameterized by LAYER.
// ---------------------------------------------------------------------------
template<int LAYER>
__global__ __launch_bounds__(256)
void gather_kernel(const float* __restrict__ bias,
                   float* __restrict__ out, int n)
{
    const __half* __restrict__ xp  = (LAYER == 1) ? g_xp1 : g_xp2;
    const float*  __restrict__ als = (LAYER == 1) ? g_als1 : g_als2;
    const float*  __restrict__ ald = (LAYER == 1) ? g_ald1 : g_ald2;

    int warp = (blockIdx.x * 256 + threadIdx.x) >> 5;
    int lane = threadIdx.x & 31;
    if (warp >= n) return;
    const int node = warp;
    const int h  = lane >> 4;
    const int hl = lane & 15;

    const __half2* __restrict__ xp2v =
        reinterpret_cast<const __half2*>(xp) + lane;

    const float ald_h = __ldg(&ald[node * 2 + h]);

    float t0 = __ldg(&als[node * 2 + h]) + ald_h;
    t0 = fmaxf(t0, 0.2f * t0);
    float wself = __expf(t0);
    float2 xv = __half22float2(xp2v[node * 32]);
    float a0 = xv.x * wself, a1 = xv.y * wself;
    float segl = 0.f;

    const int beg = g_off[node];
    const int end = g_off[node + 1];
    for (int i = beg; i < end; i += 16) {
        int idx = i + hl;
        bool valid = idx < end;
        int sidx = valid ? __ldg(&g_srcs[idx]) : 0;
        float al = __ldg(&als[sidx * 2 + h]);
        float tt = al + ald_h;
        tt = fmaxf(tt, 0.2f * tt);
        float w = valid ? __expf(tt) : 0.f;
        segl += w;

#pragma unroll
        for (int jb = 0; jb < 16; jb += 8) {
            float  ww[8];
            float2 xs[8];
#pragma unroll
            for (int j = 0; j < 8; j++) {
                ww[j] = __shfl_sync(0xffffffffu, w,    jb + j, 16);
                int s = __shfl_sync(0xffffffffu, sidx, jb + j, 16);
                xs[j] = __half22float2(xp2v[s * 32]);
            }
#pragma unroll
            for (int j = 0; j < 8; j++) {
                a0 = fmaf(xs[j].x, ww[j], a0);
                a1 = fmaf(xs[j].y, ww[j], a1);
            }
        }
    }

#pragma unroll
    for (int off = 8; off; off >>= 1)
        segl += __shfl_xor_sync(0xffffffffu, segl, off, 16);
    float seg = segl + wself;

    float inv = 1.f / (seg + 1e-16f);
    float2 bv = *(const float2*)&bias[lane * 2];
    float v0 = a0 * inv + bv.x;
    float v1 = a1 * inv + bv.y;
    if (LAYER == 1) {
        v0 = v0 > 0.f ? v0 : expm1f(v0);
        v1 = v1 > 0.f ? v1 : expm1f(v1);
        *(float2*)&g_h[node * HID + lane * 2] = make_float2(v0, v1);
    } else {
        *(float2*)&out[node * HID + lane * 2] = make_float2(v0, v1);
    }
}

extern "C" void kernel_launch(void* const* d_in, const int* in_sizes, int n_in,
                              void* d_out, int out_size)
{
    const float* x   = (const float*)d_in[0];
    const int*   ei  = (const int*)d_in[1];
    const float* W1  = (const float*)d_in[2];
    const float* as1 = (const float*)d_in[3];
    const float* ad1 = (const float*)d_in[4];
    const float* b1  = (const float*)d_in[5];
    const float* W2  = (const float*)d_in[6];
    const float* as2 = (const float*)d_in[7];
    const float* ad2 = (const float*)d_in[8];
    const float* b2  = (const float*)d_in[9];

    const int n = in_sizes[0] / 128;          // 100000
    const int E = in_sizes[1] / 2;            // 1600000
    const int gb  = (n + 127) / 128;
    const int nbl = (n + 255) / 256;
    const int ebl = (E + 255) / 256;
    const int wbl = ((n * 32) + 255) / 256;
    const int sb  = (n + SCAN_CHUNK - 1) / SCAN_CHUNK;

    static cudaStream_t sCsr = nullptr, sMain = nullptr;
    static cudaEvent_t evFork = nullptr, evCsr = nullptr, evDone = nullptr;
    if (!sCsr) {
        cudaStreamCreateWithFlags(&sCsr,  cudaStreamNonBlocking);
        cudaStreamCreateWithFlags(&sMain, cudaStreamNonBlocking);
        cudaEventCreateWithFlags(&evFork, cudaEventDisableTiming);
        cudaEventCreateWithFlags(&evCsr,  cudaEventDisableTiming);
        cudaEventCreateWithFlags(&evDone, cudaEventDisableTiming);
    }

    cudaEventRecord(evFork, 0);
    cudaStreamWaitEvent(sCsr,  evFork, 0);
    cudaStreamWaitEvent(sMain, evFork, 0);

    // CSR chain on sCsr; gemm1 concurrently on sMain
    detect_zero_kernel<<<nbl, 256, 0, sCsr>>>(ei, n);
    hist_kernel<<<ebl, 256, 0, sCsr>>>(ei, E);
    gemm_al_kernel<128, 1><<<gb, 256, 0, sMain>>>(x, W1, as1, ad1, n);
    scan_lookback<<<sb, 256, 0, sCsr>>>(n, E);
    scatter_kernel<<<ebl, 256, 0, sCsr>>>(ei, E);
    cudaEventRecord(evCsr, sCsr);

    // join: gather1 needs both gemm1 and the CSR
    cudaStreamWaitEvent(sMain, evCsr, 0);
    gather_kernel<1><<<wbl, 256, 0, sMain>>>(b1, nullptr, n);
    gemm_al_kernel<64, 2><<<gb, 256, 0, sMain>>>(x, W2, as2, ad2, n);
    gather_kernel<2><<<wbl, 256, 0, sMain>>>(b2, (float*)d_out, n);

    cudaEventRecord(evDone, sMain);
    cudaStreamWaitEvent(0, evDone, 0);
}